// round 2
// baseline (speedup 1.0000x reference)
#include <cuda_runtime.h>
#include <cstdint>

// Problem constants (hardcoded per setup_inputs)
#define BB 16
#define SS 4096
#define SK 4097   // S+1
#define DD 1024
#define HH 16
#define HD 64
#define SP 4112   // padded scores pitch

// ---------------- scratch (device globals; no allocation) ----------------
__device__ float g_q[BB * DD];            // projected+scaled q
__device__ float g_R[BB * HH * DD];       // r[b][h][d] = Wk_h^T q_bh
__device__ float g_sc[BB * HH * SP];      // scores -> attn (in place)
__device__ float g_W[BB * HH * DD];       // attn-weighted sum of comb_value
__device__ float g_ctx[BB * DD];          // ctx before out-proj

// ---------------- A1: q = (query @ Wq^T + bq) * hd^-0.5 ----------------
// warp-per-output, 16384 outputs
__global__ void k_qproj(const float* __restrict__ query,
                        const float* __restrict__ w_in,
                        const float* __restrict__ b_in) {
    int o = blockIdx.x * 8 + (threadIdx.x >> 5);
    int lane = threadIdx.x & 31;
    int b = o & 15, i = o >> 4;
    const float* qr = query + b * DD;
    const float* wr = w_in + (size_t)i * DD;
    float acc = 0.f;
    #pragma unroll
    for (int k = lane * 4; k < DD; k += 128) {
        float4 a = *(const float4*)(qr + k);
        float4 w = *(const float4*)(wr + k);
        acc += a.x * w.x + a.y * w.y + a.z * w.z + a.w * w.w;
    }
    #pragma unroll
    for (int off = 16; off; off >>= 1) acc += __shfl_down_sync(0xffffffffu, acc, off);
    if (lane == 0) g_q[b * DD + i] = (acc + b_in[i]) * 0.125f;  // hd^-0.5 = 1/8
}

// ---------------- A2: r[b][h][d] = sum_j Wk[h*64+j][d]*q[b][h*64+j]; also zero g_W
__global__ void k_rproj(const float* __restrict__ w_in) {
    int b = blockIdx.x >> 4, h = blockIdx.x & 15;
    int t = threadIdx.x;  // 256
    __shared__ float qh[HD];
    if (t < HD) qh[t] = g_q[b * DD + h * HD + t];
    *(float4*)&g_W[(b * HH + h) * DD + 4 * t] = make_float4(0.f, 0.f, 0.f, 0.f);
    __syncthreads();
    float4 acc = make_float4(0.f, 0.f, 0.f, 0.f);
    const float* wk = w_in + (size_t)(DD + h * HD) * DD + 4 * t;
    #pragma unroll 8
    for (int j = 0; j < HD; j++) {
        float4 w = *(const float4*)(wk + (size_t)j * DD);
        float qv = qh[j];
        acc.x += w.x * qv; acc.y += w.y * qv; acc.z += w.z * qv; acc.w += w.w * qv;
    }
    *(float4*)&g_R[(b * HH + h) * DD + 4 * t] = acc;
}

// ---------------- B: fused copy past_key->comb_key + scores = R . CK ----------
// grid (33, 16); 128 threads. s-tile 128, d-chunk 64.
__global__ void __launch_bounds__(128) k_scores_copyk(
    const float* __restrict__ past_key, const float* __restrict__ key,
    float* __restrict__ comb_key) {
    const int b = blockIdx.y;
    const int s0 = blockIdx.x * 128;
    const int t = threadIdx.x;
    __shared__ float Rt[HH][69];
    __shared__ float CKt[128][69];
    float acc[4][4] = {};
    const int hgrp = t >> 5, sgrp = t & 31;
    const bool fast = (s0 + 128 <= SS);

    for (int dc = 0; dc < DD; dc += 64) {
        // load R tile (16 x 64)
        #pragma unroll
        for (int p = 0; p < 2; p++) {
            int idx = p * 128 + t;
            int row = idx >> 4, c4 = (idx & 15) * 4;
            float4 v = *(const float4*)&g_R[(size_t)(b * HH + row) * DD + dc + c4];
            Rt[row][c4] = v.x; Rt[row][c4 + 1] = v.y; Rt[row][c4 + 2] = v.z; Rt[row][c4 + 3] = v.w;
        }
        // load CK tile (128 x 64) from gmem, write-through to comb_key
        #pragma unroll
        for (int p = 0; p < 16; p++) {
            int row = p * 8 + (t >> 4);
            int c4 = (t & 15) * 4;
            int s = s0 + row;
            float4 v;
            if (fast || s < SS) {
                v = *(const float4*)&past_key[((size_t)b * SS + s) * DD + dc + c4];
                *(float4*)&comb_key[((size_t)b * SK + s) * DD + dc + c4] = v;
            } else if (s == SS) {
                v = *(const float4*)&key[b * DD + dc + c4];
                *(float4*)&comb_key[((size_t)b * SK + s) * DD + dc + c4] = v;
            } else {
                v = make_float4(0.f, 0.f, 0.f, 0.f);
            }
            CKt[row][c4] = v.x; CKt[row][c4 + 1] = v.y; CKt[row][c4 + 2] = v.z; CKt[row][c4 + 3] = v.w;
        }
        __syncthreads();
        // GEMM: thread owns 4 heads (hgrp*4..) x 4 s (sgrp + 32j)
        #pragma unroll 8
        for (int dd = 0; dd < 64; dd++) {
            float rr0 = Rt[hgrp * 4 + 0][dd];
            float rr1 = Rt[hgrp * 4 + 1][dd];
            float rr2 = Rt[hgrp * 4 + 2][dd];
            float rr3 = Rt[hgrp * 4 + 3][dd];
            float cc0 = CKt[sgrp][dd];
            float cc1 = CKt[sgrp + 32][dd];
            float cc2 = CKt[sgrp + 64][dd];
            float cc3 = CKt[sgrp + 96][dd];
            acc[0][0] += rr0 * cc0; acc[0][1] += rr0 * cc1; acc[0][2] += rr0 * cc2; acc[0][3] += rr0 * cc3;
            acc[1][0] += rr1 * cc0; acc[1][1] += rr1 * cc1; acc[1][2] += rr1 * cc2; acc[1][3] += rr1 * cc3;
            acc[2][0] += rr2 * cc0; acc[2][1] += rr2 * cc1; acc[2][2] += rr2 * cc2; acc[2][3] += rr2 * cc3;
            acc[3][0] += rr3 * cc0; acc[3][1] += rr3 * cc1; acc[3][2] += rr3 * cc2; acc[3][3] += rr3 * cc3;
        }
        __syncthreads();
    }
    #pragma unroll
    for (int i = 0; i < 4; i++) {
        int h = hgrp * 4 + i;
        #pragma unroll
        for (int j = 0; j < 4; j++) {
            int s = s0 + sgrp + 32 * j;
            if (s < SK) g_sc[(size_t)(b * HH + h) * SP + s] = acc[i][j];
        }
    }
}

// ---------------- C: softmax over s (4097) per (b,h), in place -------------
__global__ void k_softmax() {
    int b = blockIdx.x >> 4, h = blockIdx.x & 15;
    float* sc = g_sc + (size_t)(b * HH + h) * SP;
    __shared__ float buf[SK];
    __shared__ float red[256];
    int t = threadIdx.x;
    float m = -1e30f;
    for (int i = t; i < SK; i += 256) { float v = sc[i]; buf[i] = v; m = fmaxf(m, v); }
    red[t] = m; __syncthreads();
    for (int o = 128; o; o >>= 1) { if (t < o) red[t] = fmaxf(red[t], red[t + o]); __syncthreads(); }
    m = red[0]; __syncthreads();
    float s = 0.f;
    for (int i = t; i < SK; i += 256) { float e = __expf(buf[i] - m); buf[i] = e; s += e; }
    red[t] = s; __syncthreads();
    for (int o = 128; o; o >>= 1) { if (t < o) red[t] += red[t + o]; __syncthreads(); }
    float inv = 1.f / red[0];
    __syncthreads();
    for (int i = t; i < SK; i += 256) sc[i] = buf[i] * inv;
}

// ---------------- D: fused copy past_value->comb_value + W = attn @ CV ------
// grid (17, 16); 256 threads; thread owns d-slice of 4 floats, 16 head accums.
__global__ void __launch_bounds__(256) k_wsum_copyv(
    const float* __restrict__ past_value, const float* __restrict__ value,
    float* __restrict__ comb_value) {
    int b = blockIdx.y;
    int s0 = blockIdx.x * 256;
    int t = threadIdx.x;
    __shared__ float At[HH][256];
    #pragma unroll
    for (int p = 0; p < 16; p++) {
        int idx = p * 256 + t;
        int h = idx >> 8, sl = idx & 255;
        int s = s0 + sl;
        At[h][sl] = (s < SK) ? g_sc[(size_t)(b * HH + h) * SP + s] : 0.f;
    }
    __syncthreads();
    float4 acc[HH];
    #pragma unroll
    for (int h = 0; h < HH; h++) acc[h] = make_float4(0.f, 0.f, 0.f, 0.f);
    const int d = 4 * t;
    const bool fast = (s0 + 256 <= SS);

    for (int sg = 0; sg < 256; sg += 4) {
        float4 cv[4];
        #pragma unroll
        for (int j = 0; j < 4; j++) {
            int s = s0 + sg + j;
            if (fast || s < SS) {
                cv[j] = *(const float4*)&past_value[((size_t)b * SS + s) * DD + d];
                *(float4*)&comb_value[((size_t)b * SK + s) * DD + d] = cv[j];
            } else if (s == SS) {
                cv[j] = *(const float4*)&value[b * DD + d];
                *(float4*)&comb_value[((size_t)b * SK + s) * DD + d] = cv[j];
            } else {
                cv[j] = make_float4(0.f, 0.f, 0.f, 0.f);
            }
        }
        #pragma unroll
        for (int h = 0; h < HH; h++) {
            float4 a = *(const float4*)&At[h][sg];
            acc[h].x += a.x * cv[0].x + a.y * cv[1].x + a.z * cv[2].x + a.w * cv[3].x;
            acc[h].y += a.x * cv[0].y + a.y * cv[1].y + a.z * cv[2].y + a.w * cv[3].y;
            acc[h].z += a.x * cv[0].z + a.y * cv[1].z + a.z * cv[2].z + a.w * cv[3].z;
            acc[h].w += a.x * cv[0].w + a.y * cv[1].w + a.z * cv[2].w + a.w * cv[3].w;
        }
    }
    #pragma unroll
    for (int h = 0; h < HH; h++) {
        float* w = &g_W[(size_t)(b * HH + h) * DD + d];
        atomicAdd(w + 0, acc[h].x);
        atomicAdd(w + 1, acc[h].y);
        atomicAdd(w + 2, acc[h].z);
        atomicAdd(w + 3, acc[h].w);
    }
}

// ---------------- E1: ctx[b][i] = Wv[i].W[b][h(i)] + bv[i] ------------------
__global__ void k_ctxproj(const float* __restrict__ w_in,
                          const float* __restrict__ b_in) {
    int o = blockIdx.x * 8 + (threadIdx.x >> 5);
    int lane = threadIdx.x & 31;
    int b = o & 15, i = o >> 4, h = i >> 6;
    const float* wv = w_in + (size_t)(2 * DD + i) * DD;
    const float* Wb = g_W + (size_t)(b * HH + h) * DD;
    float acc = 0.f;
    #pragma unroll
    for (int k = lane * 4; k < DD; k += 128) {
        float4 a = *(const float4*)(wv + k);
        float4 w = *(const float4*)(Wb + k);
        acc += a.x * w.x + a.y * w.y + a.z * w.z + a.w * w.w;
    }
    #pragma unroll
    for (int off = 16; off; off >>= 1) acc += __shfl_down_sync(0xffffffffu, acc, off);
    if (lane == 0) g_ctx[b * DD + i] = acc + b_in[2 * DD + i];
}

// ---------------- E2: out = ctx @ Wo^T + bo ---------------------------------
__global__ void k_outproj(const float* __restrict__ w_out,
                          const float* __restrict__ b_out,
                          float* __restrict__ out) {
    int o = blockIdx.x * 8 + (threadIdx.x >> 5);
    int lane = threadIdx.x & 31;
    int b = o & 15, i = o >> 4;
    const float* wr = w_out + (size_t)i * DD;
    const float* cx = g_ctx + b * DD;
    float acc = 0.f;
    #pragma unroll
    for (int k = lane * 4; k < DD; k += 128) {
        float4 a = *(const float4*)(wr + k);
        float4 w = *(const float4*)(cx + k);
        acc += a.x * w.x + a.y * w.y + a.z * w.z + a.w * w.w;
    }
    #pragma unroll
    for (int off = 16; off; off >>= 1) acc += __shfl_down_sync(0xffffffffu, acc, off);
    if (lane == 0) out[b * DD + i] = acc + b_out[i];
}

// ---------------- launch -----------------------------------------------------
extern "C" void kernel_launch(void* const* d_in, const int* in_sizes, int n_in,
                              void* d_out, int out_size) {
    const float* query      = (const float*)d_in[0];
    const float* key        = (const float*)d_in[1];
    const float* value      = (const float*)d_in[2];
    const float* past_key   = (const float*)d_in[3];
    const float* past_value = (const float*)d_in[4];
    const float* w_in       = (const float*)d_in[5];
    const float* b_in       = (const float*)d_in[6];
    const float* w_out      = (const float*)d_in[7];
    const float* b_out      = (const float*)d_in[8];

    float* out        = (float*)d_out;                       // (16,1,1024)
    float* comb_key   = out + (size_t)BB * DD;               // (16,4097,1024)
    float* comb_value = comb_key + (size_t)BB * SK * DD;     // (16,4097,1024)

    k_qproj<<<2048, 256>>>(query, w_in, b_in);
    k_rproj<<<256, 256>>>(w_in);
    k_scores_copyk<<<dim3(33, 16), 128>>>(past_key, key, comb_key);
    k_softmax<<<256, 256>>>();
    k_wsum_copyv<<<dim3(17, 16), 256>>>(past_value, value, comb_value);
    k_ctxproj<<<2048, 256>>>(w_in, b_in);
    k_outproj<<<2048, 256>>>(w_out, b_out, out);
}